// round 2
// baseline (speedup 1.0000x reference)
#include <cuda_runtime.h>
#include <cuda_bf16.h>

// RFFT2d: x (32,1,1024,1024) fp32 -> out (32, 16384, 8, 5, 2) fp32
// 8x8 blocks, length-8 rFFT along each block row, scaled by 1/64.
//
// One thread per block-row (8 input floats -> 5 complex = 10 output floats).
// Thread mapping puts r (row-in-block) fastest so warp writes are one
// contiguous 1280B span; reads are two aligned float4 per thread.

#define TOTAL_ROWS (32u * 128u * 128u * 8u)  // 4,194,304

__global__ __launch_bounds__(256) void rfft8_kernel(
    const float* __restrict__ in, float* __restrict__ out)
{
    unsigned tid = blockIdx.x * blockDim.x + threadIdx.x;
    // tid < 4194304 guaranteed by exact grid sizing

    unsigned r   = tid & 7u;           // row within 8x8 block
    unsigned bw  = (tid >> 3) & 127u;  // block col
    unsigned nbh = tid >> 10;          // n*128 + bh  (0..4095)

    // input row = (n*128 + bh)*8 + r, row stride 1024 floats
    unsigned in_off = (nbh * 8u + r) * 1024u + bw * 8u;

    const float4* p = reinterpret_cast<const float4*>(in + in_off);
    float4 v0 = p[0];
    float4 v1 = p[1];

    float x0 = v0.x, x1 = v0.y, x2 = v0.z, x3 = v0.w;
    float x4 = v1.x, x5 = v1.y, x6 = v1.z, x7 = v1.w;

    const float s   = 0.70710678118654752440f;
    const float scl = 1.0f / 64.0f;

    float a = x0 + x4, b = x0 - x4;
    float c = x2 + x6, d = x2 - x6;
    float e = x1 + x5, f = x1 - x5;
    float g = x3 + x7, h = x3 - x7;

    float fmh = f - h;   // f - h
    float fph = f + h;   // f + h

    float X0r = (a + c) + (e + g);
    float X4r = (a + c) - (e + g);
    float X2r = a - c;
    float X2i = g - e;
    float sfmh = s * fmh;
    float sfph = s * fph;
    float X1r = b + sfmh;
    float X1i = -sfph - d;
    float X3r = b - sfmh;
    float X3i = d - sfph;

    // output: 10 contiguous floats at float-offset tid*10 (8B aligned)
    float* o = out + (size_t)tid * 10u;
    float2* o2 = reinterpret_cast<float2*>(o);
    o2[0] = make_float2(X0r * scl, 0.0f);
    o2[1] = make_float2(X1r * scl, X1i * scl);
    o2[2] = make_float2(X2r * scl, X2i * scl);
    o2[3] = make_float2(X3r * scl, X3i * scl);
    o2[4] = make_float2(X4r * scl, 0.0f);
}

extern "C" void kernel_launch(void* const* d_in, const int* in_sizes, int n_in,
                              void* d_out, int out_size)
{
    const float* x = (const float*)d_in[0];
    float* out = (float*)d_out;
    const unsigned threads = 256;
    const unsigned blocks = TOTAL_ROWS / threads;  // 16384
    rfft8_kernel<<<blocks, threads>>>(x, out);
}

// round 3
// speedup vs baseline: 1.2902x; 1.2902x over previous
#include <cuda_runtime.h>
#include <cuda_bf16.h>

// RFFT2d: x (32,1,1024,1024) fp32 -> out (32, 16384, 8, 5, 2) fp32
// 8x8 blocks, length-8 rFFT along each block row, scaled by 1/64.
//
// One thread per block-row. Reads: two aligned float4 LDGs (sector-efficient:
// same-r threads share 128B lines). Writes: staged through shared memory so
// the global drain is dense, warp-coalesced STG.128 (fixes the 4x L2 store
// amplification of the 40B-stride direct-store version).

#define TOTAL_ROWS (32u * 128u * 128u * 8u)  // 4,194,304

__global__ __launch_bounds__(256) void rfft8_kernel(
    const float* __restrict__ in, float* __restrict__ out)
{
    __shared__ float sm[2560];  // 256 threads * 10 output floats

    unsigned t   = threadIdx.x;
    unsigned tid = blockIdx.x * 256u + t;

    unsigned r   = tid & 7u;           // row within 8x8 block
    unsigned bw  = (tid >> 3) & 127u;  // block col
    unsigned nbh = tid >> 10;          // n*128 + bh

    unsigned in_off = (nbh * 8u + r) * 1024u + bw * 8u;

    const float4* p = reinterpret_cast<const float4*>(in + in_off);
    float4 v0 = p[0];
    float4 v1 = p[1];

    float x0 = v0.x, x1 = v0.y, x2 = v0.z, x3 = v0.w;
    float x4 = v1.x, x5 = v1.y, x6 = v1.z, x7 = v1.w;

    const float s   = 0.70710678118654752440f;
    const float scl = 1.0f / 64.0f;

    float a = x0 + x4, b = x0 - x4;
    float c = x2 + x6, d = x2 - x6;
    float e = x1 + x5, f = x1 - x5;
    float g = x3 + x7, h = x3 - x7;

    float fmh = f - h;
    float fph = f + h;

    float X0r = (a + c) + (e + g);
    float X4r = (a + c) - (e + g);
    float X2r = a - c;
    float X2i = g - e;
    float sfmh = s * fmh;
    float sfph = s * fph;
    float X1r = b + sfmh;
    float X1i = -sfph - d;
    float X3r = b - sfmh;
    float X3i = d - sfph;

    // Stage 10 floats into smem at t*10 (8B aligned -> float2 stores)
    float2* so = reinterpret_cast<float2*>(sm + t * 10u);
    so[0] = make_float2(X0r * scl, 0.0f);
    so[1] = make_float2(X1r * scl, X1i * scl);
    so[2] = make_float2(X2r * scl, X2i * scl);
    so[3] = make_float2(X3r * scl, X3i * scl);
    so[4] = make_float2(X4r * scl, 0.0f);

    __syncthreads();

    // Dense drain: 2560 floats = 640 float4, perfectly coalesced per warp.
    const float4* sm4 = reinterpret_cast<const float4*>(sm);
    float4* out4 = reinterpret_cast<float4*>(out) + (size_t)blockIdx.x * 640u;
#pragma unroll
    for (unsigned k = t; k < 640u; k += 256u) {
        out4[k] = sm4[k];
    }
}

extern "C" void kernel_launch(void* const* d_in, const int* in_sizes, int n_in,
                              void* d_out, int out_size)
{
    const float* x = (const float*)d_in[0];
    float* out = (float*)d_out;
    const unsigned threads = 256;
    const unsigned blocks = TOTAL_ROWS / threads;  // 16384
    rfft8_kernel<<<blocks, threads>>>(x, out);
}

// round 4
// speedup vs baseline: 1.2909x; 1.0005x over previous
#include <cuda_runtime.h>
#include <cuda_bf16.h>

// RFFT2d: x (32,1,1024,1024) fp32 -> out (32, 16384, 8, 5, 2) fp32
// 8x8 blocks, length-8 rFFT along each block row, scaled by 1/64.
//
// One thread per block-row. Reads: two aligned float4 LDGs (sector-efficient:
// same-r threads share 128B lines). Writes: staged through shared memory so
// the global drain is dense, warp-coalesced STG.128 (fixes the 4x L2 store
// amplification of the 40B-stride direct-store version).

#define TOTAL_ROWS (32u * 128u * 128u * 8u)  // 4,194,304

__global__ __launch_bounds__(256) void rfft8_kernel(
    const float* __restrict__ in, float* __restrict__ out)
{
    __shared__ float sm[2560];  // 256 threads * 10 output floats

    unsigned t   = threadIdx.x;
    unsigned tid = blockIdx.x * 256u + t;

    unsigned r   = tid & 7u;           // row within 8x8 block
    unsigned bw  = (tid >> 3) & 127u;  // block col
    unsigned nbh = tid >> 10;          // n*128 + bh

    unsigned in_off = (nbh * 8u + r) * 1024u + bw * 8u;

    const float4* p = reinterpret_cast<const float4*>(in + in_off);
    float4 v0 = p[0];
    float4 v1 = p[1];

    float x0 = v0.x, x1 = v0.y, x2 = v0.z, x3 = v0.w;
    float x4 = v1.x, x5 = v1.y, x6 = v1.z, x7 = v1.w;

    const float s   = 0.70710678118654752440f;
    const float scl = 1.0f / 64.0f;

    float a = x0 + x4, b = x0 - x4;
    float c = x2 + x6, d = x2 - x6;
    float e = x1 + x5, f = x1 - x5;
    float g = x3 + x7, h = x3 - x7;

    float fmh = f - h;
    float fph = f + h;

    float X0r = (a + c) + (e + g);
    float X4r = (a + c) - (e + g);
    float X2r = a - c;
    float X2i = g - e;
    float sfmh = s * fmh;
    float sfph = s * fph;
    float X1r = b + sfmh;
    float X1i = -sfph - d;
    float X3r = b - sfmh;
    float X3i = d - sfph;

    // Stage 10 floats into smem at t*10 (8B aligned -> float2 stores)
    float2* so = reinterpret_cast<float2*>(sm + t * 10u);
    so[0] = make_float2(X0r * scl, 0.0f);
    so[1] = make_float2(X1r * scl, X1i * scl);
    so[2] = make_float2(X2r * scl, X2i * scl);
    so[3] = make_float2(X3r * scl, X3i * scl);
    so[4] = make_float2(X4r * scl, 0.0f);

    __syncthreads();

    // Dense drain: 2560 floats = 640 float4, perfectly coalesced per warp.
    const float4* sm4 = reinterpret_cast<const float4*>(sm);
    float4* out4 = reinterpret_cast<float4*>(out) + (size_t)blockIdx.x * 640u;
#pragma unroll
    for (unsigned k = t; k < 640u; k += 256u) {
        out4[k] = sm4[k];
    }
}

extern "C" void kernel_launch(void* const* d_in, const int* in_sizes, int n_in,
                              void* d_out, int out_size)
{
    const float* x = (const float*)d_in[0];
    float* out = (float*)d_out;
    const unsigned threads = 256;
    const unsigned blocks = TOTAL_ROWS / threads;  // 16384
    rfft8_kernel<<<blocks, threads>>>(x, out);
}

// round 5
// speedup vs baseline: 1.4844x; 1.1499x over previous
#include <cuda_runtime.h>
#include <cuda_bf16.h>
#include <cstdint>

// RFFT2d: x (32,1,1024,1024) fp32 -> out (32, 16384, 8, 5, 2) fp32
// 8x8 blocks, length-8 rFFT along each block row, scaled by 1/64.
//
// One thread per block-row. Reads: two aligned float4 LDGs. Outputs staged in
// smem (conflict-free STS.64 at 10-float stride), then drained by ONE
// cp.async.bulk (TMA bulk store) per CTA -> removes all LDS/STG drain
// wavefronts from the l1tex path (which was the binding pipe at 76%).

#define TOTAL_ROWS (32u * 128u * 128u * 8u)  // 4,194,304

__global__ __launch_bounds__(256) void rfft8_kernel(
    const float* __restrict__ in, float* __restrict__ out)
{
    __shared__ __align__(16) float sm[2560];  // 256 rows * 10 floats = 10240B

    unsigned t   = threadIdx.x;
    unsigned tid = blockIdx.x * 256u + t;

    unsigned r   = tid & 7u;           // row within 8x8 block
    unsigned bw  = (tid >> 3) & 127u;  // block col
    unsigned nbh = tid >> 10;          // n*128 + bh

    unsigned in_off = (nbh * 8u + r) * 1024u + bw * 8u;

    const float4* p = reinterpret_cast<const float4*>(in + in_off);
    float4 v0 = p[0];
    float4 v1 = p[1];

    float x0 = v0.x, x1 = v0.y, x2 = v0.z, x3 = v0.w;
    float x4 = v1.x, x5 = v1.y, x6 = v1.z, x7 = v1.w;

    const float s   = 0.70710678118654752440f;
    const float scl = 1.0f / 64.0f;

    float a = x0 + x4, b = x0 - x4;
    float c = x2 + x6, d = x2 - x6;
    float e = x1 + x5, f = x1 - x5;
    float g = x3 + x7, h = x3 - x7;

    float fmh = f - h;
    float fph = f + h;

    float X0r = (a + c) + (e + g);
    float X4r = (a + c) - (e + g);
    float X2r = a - c;
    float X2i = g - e;
    float sfmh = s * fmh;
    float sfph = s * fph;
    float X1r = b + sfmh;
    float X1i = -sfph - d;
    float X3r = b - sfmh;
    float X3i = d - sfph;

    // Stage 10 floats into smem at t*10 (8B aligned; 10-float stride is
    // bank-conflict-free for STG.64 half-warp phases).
    float2* so = reinterpret_cast<float2*>(sm + t * 10u);
    so[0] = make_float2(X0r * scl, 0.0f);
    so[1] = make_float2(X1r * scl, X1i * scl);
    so[2] = make_float2(X2r * scl, X2i * scl);
    so[3] = make_float2(X3r * scl, X3i * scl);
    so[4] = make_float2(X4r * scl, 0.0f);

    // Make generic-proxy smem writes visible to the async (TMA) proxy.
    asm volatile("fence.proxy.async.shared::cta;" ::: "memory");
    __syncthreads();

    if (t == 0) {
        // smem generic -> shared address
        uint32_t saddr;
        asm("{ .reg .u64 tmp; cvta.to.shared.u64 tmp, %1; cvt.u32.u64 %0, tmp; }"
            : "=r"(saddr) : "l"(sm));
        float* dst = out + (size_t)blockIdx.x * 2560u;
        asm volatile(
            "cp.async.bulk.global.shared::cta.bulk_group [%0], [%1], %2;"
            :: "l"(dst), "r"(saddr), "r"(10240u) : "memory");
        asm volatile("cp.async.bulk.commit_group;" ::: "memory");
        // Must complete before CTA teardown frees the smem source.
        asm volatile("cp.async.bulk.wait_group 0;" ::: "memory");
    }
}

extern "C" void kernel_launch(void* const* d_in, const int* in_sizes, int n_in,
                              void* d_out, int out_size)
{
    const float* x = (const float*)d_in[0];
    float* out = (float*)d_out;
    const unsigned threads = 256;
    const unsigned blocks = TOTAL_ROWS / threads;  // 16384
    rfft8_kernel<<<blocks, threads>>>(x, out);
}

// round 7
// speedup vs baseline: 1.5368x; 1.0354x over previous
#include <cuda_runtime.h>
#include <cuda_bf16.h>
#include <cstdint>

// RFFT2d: x (32,1,1024,1024) fp32 -> out (32, 16384, 8, 5, 2) fp32
// 8x8 blocks, length-8 rFFT along each block row, scaled by 1/64.
//
// Two rows per thread (rows t and t+256 of a 512-row CTA tile): 4 independent
// LDG.128 issued up front (MLP=4) to raise DRAM utilization; outputs staged in
// smem and drained by one 20KB cp.async.bulk per CTA.

#define TOTAL_ROWS (32u * 128u * 128u * 8u)  // 4,194,304
#define ROWS_PER_CTA 512u

__device__ __forceinline__ void rfft8_row(
    float x0, float x1, float x2, float x3,
    float x4, float x5, float x6, float x7,
    float* sm_row)
{
    const float s   = 0.70710678118654752440f;
    const float scl = 1.0f / 64.0f;

    float a = x0 + x4, b = x0 - x4;
    float c = x2 + x6, d = x2 - x6;
    float e = x1 + x5, f = x1 - x5;
    float g = x3 + x7, h = x3 - x7;

    float fmh = f - h;
    float fph = f + h;

    float X0r = (a + c) + (e + g);
    float X4r = (a + c) - (e + g);
    float X2r = a - c;
    float X2i = g - e;
    float sfmh = s * fmh;
    float sfph = s * fph;
    float X1r = b + sfmh;
    float X1i = -sfph - d;
    float X3r = b - sfmh;
    float X3i = d - sfph;

    float2* so = reinterpret_cast<float2*>(sm_row);
    so[0] = make_float2(X0r * scl, 0.0f);
    so[1] = make_float2(X1r * scl, X1i * scl);
    so[2] = make_float2(X2r * scl, X2i * scl);
    so[3] = make_float2(X3r * scl, X3i * scl);
    so[4] = make_float2(X4r * scl, 0.0f);
}

__global__ __launch_bounds__(256) void rfft8_kernel(
    const float* __restrict__ in, float* __restrict__ out)
{
    __shared__ __align__(16) float sm[ROWS_PER_CTA * 10u];  // 20480 B

    unsigned t   = threadIdx.x;
    unsigned row = blockIdx.x * ROWS_PER_CTA + t;   // first row for this thread
    // second row = row + 256 (same nbh since 512 | 1024; in_off2 = in_off + 1KB)

    unsigned r   = row & 7u;
    unsigned bw  = (row >> 3) & 127u;
    unsigned nbh = row >> 10;

    unsigned in_off = (nbh * 8u + r) * 1024u + bw * 8u;

    const float4* p = reinterpret_cast<const float4*>(in + in_off);
    // Issue all four loads before any compute (MLP = 4).
    float4 a0 = p[0];
    float4 a1 = p[1];
    float4 b0 = p[64];   // +256 floats = +32 bw blocks = row + 256
    float4 b1 = p[65];

    rfft8_row(a0.x, a0.y, a0.z, a0.w, a1.x, a1.y, a1.z, a1.w,
              sm + t * 10u);
    rfft8_row(b0.x, b0.y, b0.z, b0.w, b1.x, b1.y, b1.z, b1.w,
              sm + (t + 256u) * 10u);

    // Make generic-proxy smem writes visible to the async (TMA) proxy.
    asm volatile("fence.proxy.async.shared::cta;" ::: "memory");
    __syncthreads();

    if (t == 0) {
        uint32_t saddr;
        asm("{ .reg .u64 tmp; cvta.to.shared.u64 tmp, %1; cvt.u32.u64 %0, tmp; }"
            : "=r"(saddr) : "l"(sm));
        float* dst = out + (size_t)blockIdx.x * (ROWS_PER_CTA * 10u);
        asm volatile(
            "cp.async.bulk.global.shared::cta.bulk_group [%0], [%1], %2;"
            :: "l"(dst), "r"(saddr), "r"(ROWS_PER_CTA * 40u) : "memory");
        asm volatile("cp.async.bulk.commit_group;" ::: "memory");
        asm volatile("cp.async.bulk.wait_group 0;" ::: "memory");
    }
}

extern "C" void kernel_launch(void* const* d_in, const int* in_sizes, int n_in,
                              void* d_out, int out_size)
{
    const float* x = (const float*)d_in[0];
    float* out = (float*)d_out;
    const unsigned threads = 256;
    const unsigned blocks = TOTAL_ROWS / ROWS_PER_CTA;  // 8192
    rfft8_kernel<<<blocks, threads>>>(x, out);
}

// round 8
// speedup vs baseline: 1.6667x; 1.0845x over previous
#include <cuda_runtime.h>
#include <cuda_bf16.h>
#include <cstdint>

// RFFT2d: x (32,1,1024,1024) fp32 -> out (32, 16384, 8, 5, 2) fp32
// 8x8 blocks, length-8 rFFT along each block row, scaled by 1/64.
//
// Dense warp loads (each LDG.128 covers 4 fully-consumed 128B lines) +
// __shfl redistribution to the owning thread -> halves read-side l1tex
// wavefronts vs the strided own-row loads. Outputs staged in smem
// (conflict-free STS, lanes own consecutive output rows) and drained by
// one 20KB cp.async.bulk per CTA.

#define TOTAL_ROWS (32u * 128u * 128u * 8u)  // 4,194,304
#define ROWS_PER_CTA 512u

__device__ __forceinline__ float4 shfl4(float4 v, unsigned src) {
    float4 r;
    r.x = __shfl_sync(0xffffffffu, v.x, src);
    r.y = __shfl_sync(0xffffffffu, v.y, src);
    r.z = __shfl_sync(0xffffffffu, v.z, src);
    r.w = __shfl_sync(0xffffffffu, v.w, src);
    return r;
}

__device__ __forceinline__ void rfft8_row(float4 v0, float4 v1, float* sm_row)
{
    float x0 = v0.x, x1 = v0.y, x2 = v0.z, x3 = v0.w;
    float x4 = v1.x, x5 = v1.y, x6 = v1.z, x7 = v1.w;

    const float s   = 0.70710678118654752440f;
    const float scl = 1.0f / 64.0f;

    float a = x0 + x4, b = x0 - x4;
    float c = x2 + x6, d = x2 - x6;
    float e = x1 + x5, f = x1 - x5;
    float g = x3 + x7, h = x3 - x7;

    float fmh = f - h;
    float fph = f + h;

    float X0r = (a + c) + (e + g);
    float X4r = (a + c) - (e + g);
    float X2r = a - c;
    float X2i = g - e;
    float sfmh = s * fmh;
    float sfph = s * fph;
    float X1r = b + sfmh;
    float X1i = -sfph - d;
    float X3r = b - sfmh;
    float X3i = d - sfph;

    float2* so = reinterpret_cast<float2*>(sm_row);
    so[0] = make_float2(X0r * scl, 0.0f);
    so[1] = make_float2(X1r * scl, X1i * scl);
    so[2] = make_float2(X2r * scl, X2i * scl);
    so[3] = make_float2(X3r * scl, X3i * scl);
    so[4] = make_float2(X4r * scl, 0.0f);
}

__global__ __launch_bounds__(256) void rfft8_kernel(
    const float* __restrict__ in, float* __restrict__ out)
{
    __shared__ __align__(16) float sm[ROWS_PER_CTA * 10u];  // 20480 B

    unsigned t = threadIdx.x;
    unsigned w = t >> 5;     // warp 0..7
    unsigned l = t & 31u;    // lane
    unsigned B = blockIdx.x; // 0..8191
    unsigned nbh = B >> 1;   // n*128 + bh

    // Dense load mapping: lane l reads float4 (l&7) of image row (l>>3)
    // within this warp-group's 4-block span. 8 lanes fully consume one
    // 128B line -> 4 wavefronts per LDG.128.
    const float4* in4 = reinterpret_cast<const float4*>(in);
    unsigned a00 = (nbh * 8u + (l >> 3)) * 256u        // image row (load0: r' 0..3)
                 + (B & 1u) * 128u + w * 16u           // warp g=0 span base (f4)
                 + (l & 7u);

    // All four loads issued up front (MLP = 4).
    float4 L0g0 = in4[a00];          // g0, image rows 0..3
    float4 L1g0 = in4[a00 + 1024u];  // g0, image rows 4..7 (+4 rows * 256 f4)
    float4 L0g1 = in4[a00 + 8u];     // g1 span = +4 blocks = +8 f4
    float4 L1g1 = in4[a00 + 1032u];

    // Gather routing: thread owns r_own = l&7, j0 = (l>>3)*2.
    // Source lane s = (r_own&3)*8 + j0 holds (r_own mod 4, j0) in load0 and
    // (r_own mod 4 + 4, j0) in load1; pick by r_own < 4.
    unsigned s0 = (l & 3u) * 8u + ((l >> 3) << 1);
    unsigned s1 = s0 + 1u;
    bool lo = (l & 4u) == 0u;  // r_own < 4

    // Group 0: rows rho = w*64 + l
    {
        float4 A = shfl4(L0g0, s0);
        float4 Bv = shfl4(L0g0, s1);
        float4 C = shfl4(L1g0, s0);
        float4 D = shfl4(L1g0, s1);
        float4 v0 = lo ? A : C;
        float4 v1 = lo ? Bv : D;
        rfft8_row(v0, v1, sm + (w * 64u + l) * 10u);
    }
    // Group 1: rows rho = w*64 + 32 + l
    {
        float4 A = shfl4(L0g1, s0);
        float4 Bv = shfl4(L0g1, s1);
        float4 C = shfl4(L1g1, s0);
        float4 D = shfl4(L1g1, s1);
        float4 v0 = lo ? A : C;
        float4 v1 = lo ? Bv : D;
        rfft8_row(v0, v1, sm + (w * 64u + 32u + l) * 10u);
    }

    // Make generic-proxy smem writes visible to the async (TMA) proxy.
    asm volatile("fence.proxy.async.shared::cta;" ::: "memory");
    __syncthreads();

    if (t == 0) {
        uint32_t saddr;
        asm("{ .reg .u64 tmp; cvta.to.shared.u64 tmp, %1; cvt.u32.u64 %0, tmp; }"
            : "=r"(saddr) : "l"(sm));
        float* dst = out + (size_t)B * (ROWS_PER_CTA * 10u);
        asm volatile(
            "cp.async.bulk.global.shared::cta.bulk_group [%0], [%1], %2;"
            :: "l"(dst), "r"(saddr), "r"(ROWS_PER_CTA * 40u) : "memory");
        asm volatile("cp.async.bulk.commit_group;" ::: "memory");
        asm volatile("cp.async.bulk.wait_group 0;" ::: "memory");
    }
}

extern "C" void kernel_launch(void* const* d_in, const int* in_sizes, int n_in,
                              void* d_out, int out_size)
{
    const float* x = (const float*)d_in[0];
    float* out = (float*)d_out;
    const unsigned threads = 256;
    const unsigned blocks = TOTAL_ROWS / ROWS_PER_CTA;  // 8192
    rfft8_kernel<<<blocks, threads>>>(x, out);
}